// round 14
// baseline (speedup 1.0000x reference)
#include <cuda_runtime.h>
#include <cuda_fp16.h>
#include <math.h>
#include <stdint.h>

// Problem constants (fixed by the dataset)
#define NB 2
#define NN 8192
#define NF 512
#define NHD 512   // H*D
#define NH 8
#define ND 64
#define NM (NB * NN)   // 16384
#define BUCKET 64

// -------- scratch (device globals; zero-initialized at load; agg restores zeros) --------
__device__ __half g_h[NB * NN * NHD];                // 16 MB (fp16 h)
__device__ __half g_wh[NHD * NF];                    // 0.5 MB
__device__ __half g_wl[NHD * NF];                    // 0.5 MB
__device__ float g_s1[NB * NN * NH];
__device__ float g_s2[NB * NN * NH];
__device__ int   g_last[NN];                         // e+1 encoding; 0 = no edge
__device__ int   g_cnt[NN];
__device__ int   g_csr[NN * BUCKET];                 // 2 MB

// ======================= helpers =======================
__device__ __forceinline__ uint32_t smem_u32(const void* p) {
    uint32_t a;
    asm("{ .reg .u64 t; cvta.to.shared.u64 t, %1; cvt.u32.u64 %0, t; }" : "=r"(a) : "l"(p));
    return a;
}
__device__ __forceinline__ void ldsm_x4(uint32_t* r, uint32_t addr) {
    asm volatile("ldmatrix.sync.aligned.m8n8.x4.shared.b16 {%0,%1,%2,%3}, [%4];"
        : "=r"(r[0]), "=r"(r[1]), "=r"(r[2]), "=r"(r[3]) : "r"(addr));
}
__device__ __forceinline__ void mma_fp16(float* d, const uint32_t* a, const uint32_t* b) {
    asm volatile("mma.sync.aligned.m16n8k16.row.col.f32.f16.f16.f32 "
        "{%0,%1,%2,%3}, {%4,%5,%6,%7}, {%8,%9}, {%0,%1,%2,%3};"
        : "+f"(d[0]), "+f"(d[1]), "+f"(d[2]), "+f"(d[3])
        : "r"(a[0]), "r"(a[1]), "r"(a[2]), "r"(a[3]), "r"(b[0]), "r"(b[1]));
}
__device__ __forceinline__ uint32_t hpack2(__half x, __half y) {
    uint32_t lo = __half_as_ushort(x), hi = __half_as_ushort(y);
    return (hi << 16) | lo;
}
__device__ __forceinline__ void cp16(uint32_t dst, const void* src) {
    asm volatile("cp.async.cg.shared.global [%0], [%1], 16;" :: "r"(dst), "l"(src));
}
#define CP_COMMIT() asm volatile("cp.async.commit_group;" ::: "memory")
#define CP_WAIT(n)  asm volatile("cp.async.wait_group %0;" :: "n"(n) : "memory")

// ======================= prep: conv(W) + edge build =======================
#define WQ (NHD * NF / 4)
__global__ __launch_bounds__(256) void prep_kernel(
    const float* __restrict__ w, const int* __restrict__ ei, int E)
{
    int q = blockIdx.x * blockDim.x + threadIdx.x;
    if (q < WQ) {
        size_t i = (size_t)q * 4;
        float4 v = *(const float4*)(w + i);
        __half hx = __float2half_rn(v.x), hy = __float2half_rn(v.y);
        __half hz = __float2half_rn(v.z), hw = __float2half_rn(v.w);
        uint2 hi = make_uint2(hpack2(hx, hy), hpack2(hz, hw));
        uint2 lo = make_uint2(
            hpack2(__float2half_rn(v.x - __half2float(hx)),
                   __float2half_rn(v.y - __half2float(hy))),
            hpack2(__float2half_rn(v.z - __half2float(hz)),
                   __float2half_rn(v.w - __half2float(hw))));
        *(uint2*)(g_wh + i) = hi;
        *(uint2*)(g_wl + i) = lo;
    } else {
        int e = q - WQ;
        if (e < E) {
            int s = ei[e];
            atomicMax(&g_last[s], e + 1);          // +1: zero means "no edge"
            int p = atomicAdd(&g_cnt[s], 1);
            g_csr[s * BUCKET + p] = ei[E + e];
        }
    }
}

// ======================= fp16 2-term GEMM, 64x128 tile, 3 CTAs/SM =======================
// A converted f32->fp16 in-register during fill (no pre-converted x buffer).
#define TILE_A 4096
#define TILE_BB 8192
#define STAGE_B (TILE_A + 2 * TILE_BB)       // 20480: A, Bh, Bl
#define NSTAGE 3
#define GEMM_SMEM (NSTAGE * STAGE_B)         // 61440
#define NKC (NF / 32)                        // 16 chunks
#define OFF_A 0
#define OFF_BH TILE_A
#define OFF_BL (TILE_A + TILE_BB)

__global__ __launch_bounds__(256, 3) void gemm_split(
    const float* __restrict__ gx, const float* __restrict__ ga)
{
    extern __shared__ char smem[];
    const uint32_t sb = smem_u32(smem);
    const int tid = threadIdx.x, wid = tid >> 5, lid = tid & 31;
    const int m0 = blockIdx.y * 64, n0 = blockIdx.x * 128;
    const int warp_m = (wid >> 2) * 32, warp_n = (wid & 3) * 32;

    // ---- A fill: thread t -> row t>>2, 8 fp16 at cols (t&3)*8; source f32 x ----
    const int aflr = tid >> 2;
    const uint32_t afu = (uint32_t)(aflr & 1) * 4 + (tid & 3);
    const uint32_t afm = ((uint32_t)aflr >> 1) & 7;
    const uint32_t adst = ((uint32_t)(aflr >> 1)) * 128 + ((afu ^ afm) << 4);
    const float* axsrc = gx + (size_t)(m0 + aflr) * NF + (tid & 3) * 8;

    // ---- B fill ----
    const int bflr = tid >> 1, bfh = tid & 1;
    const uint32_t bfu = (uint32_t)(bflr & 1) * 4 + bfh * 2;
    const uint32_t bfm = ((uint32_t)bflr >> 1) & 7;
    const uint32_t bd0 = ((uint32_t)(bflr >> 1)) * 128 + ((bfu ^ bfm) << 4);
    const uint32_t bd1 = ((uint32_t)(bflr >> 1)) * 128 + (((bfu + 1) ^ bfm) << 4);
    const size_t  bsrc = (size_t)(n0 + bflr) * NF + bfh * 16;

    // ---- ldsm constants ----
    const int alr = warp_m + (lid & 15);
    const uint32_t a_row = ((uint32_t)(alr >> 1)) * 128;
    const uint32_t a4 = (uint32_t)(alr & 1) * 4 + (lid >> 4);
    const uint32_t amask = ((uint32_t)(alr >> 1)) & 7;
    const int blr = warp_n + (lid & 7) + (lid >> 4) * 8;
    const uint32_t b_row = ((uint32_t)(blr >> 1)) * 128;
    const uint32_t b4 = (uint32_t)(blr & 1) * 4 + ((lid >> 3) & 1);
    const uint32_t bmask = ((uint32_t)(blr >> 1)) & 7;

    float acc[2][4][4];
    #pragma unroll
    for (int i = 0; i < 2; i++)
        #pragma unroll
        for (int j = 0; j < 4; j++)
            #pragma unroll
            for (int v = 0; v < 4; v++) acc[i][j][v] = 0.f;

    float4 aF0, aF1;                 // prefetched f32 A values (8 floats)
    auto ldA = [&](int kc) {
        aF0 = *(const float4*)(axsrc + kc * 32);
        aF1 = *(const float4*)(axsrc + kc * 32 + 4);
    };
    auto stsA = [&](int s) {
        uint4 hv;
        hv.x = hpack2(__float2half_rn(aF0.x), __float2half_rn(aF0.y));
        hv.y = hpack2(__float2half_rn(aF0.z), __float2half_rn(aF0.w));
        hv.z = hpack2(__float2half_rn(aF1.x), __float2half_rn(aF1.y));
        hv.w = hpack2(__float2half_rn(aF1.z), __float2half_rn(aF1.w));
        *(uint4*)(smem + (size_t)s * STAGE_B + OFF_A + adst) = hv;
    };
    auto issueB = [&](int kc, int s) {
        const uint32_t base = sb + (uint32_t)s * STAGE_B;
        const int kcol = kc * 32;
        const __half* s2 = g_wh + bsrc + kcol;
        const __half* s3 = g_wl + bsrc + kcol;
        cp16(base + OFF_BH + bd0, s2);   cp16(base + OFF_BH + bd1, s2 + 8);
        cp16(base + OFF_BL + bd0, s3);   cp16(base + OFF_BL + bd1, s3 + 8);
        CP_COMMIT();
    };

    // prologue: A(0), A(1) converted + stored; B(0), B(1) in flight; A(2) prefetched
    ldA(0); stsA(0);
    ldA(1); stsA(1);
    issueB(0, 0);
    issueB(1, 1);
    ldA(2);

    int stg = 0;
    #pragma unroll 1
    for (int kc = 0; kc < NKC; kc++) {
        if (kc + 2 < NKC) { CP_WAIT(1); } else { CP_WAIT(0); }
        __syncthreads();
        if (kc + 2 < NKC) {
            int s2 = stg + 2; if (s2 >= NSTAGE) s2 -= NSTAGE;
            stsA(s2);                     // regs hold A(kc+2)
            issueB(kc + 2, s2);
            if (kc + 3 < NKC) ldA(kc + 3);
        }
        {
            const uint32_t base = sb + (uint32_t)stg * STAGE_B;
            const uint32_t aH = base + OFF_A + a_row;
            const uint32_t bH = base + OFF_BH + b_row;
            #pragma unroll
            for (int ks = 0; ks < 2; ks++) {
                const uint32_t axo = ((a4 + 2 * ks) ^ amask) << 4;
                const uint32_t bxo = ((b4 + 2 * ks) ^ bmask) << 4;
                uint32_t bh[2][4], bl[2][4];
                #pragma unroll
                for (int np = 0; np < 2; np++) {
                    ldsm_x4(bh[np], bH + np * 1024 + bxo);
                    ldsm_x4(bl[np], bH + TILE_BB + np * 1024 + bxo);
                }
                #pragma unroll
                for (int mt = 0; mt < 2; mt++) {
                    uint32_t ah[4];
                    ldsm_x4(ah, aH + mt * 1024 + axo);
                    #pragma unroll
                    for (int nt = 0; nt < 4; nt++) {
                        const uint32_t* bhp = &bh[nt >> 1][(nt & 1) * 2];
                        const uint32_t* blp = &bl[nt >> 1][(nt & 1) * 2];
                        mma_fp16(acc[mt][nt], ah, bhp);
                        mma_fp16(acc[mt][nt], ah, blp);
                    }
                }
            }
        }
        stg++; if (stg >= NSTAGE) stg -= NSTAGE;
    }

    // ---- epilogue 1: write C as fp16 ----
    #pragma unroll
    for (int mt = 0; mt < 2; mt++) {
        const int row0 = m0 + warp_m + mt * 16 + (lid >> 2);
        #pragma unroll
        for (int nt = 0; nt < 4; nt++) {
            const int col = n0 + warp_n + nt * 8 + (lid & 3) * 2;
            *(__half2*)(g_h + (size_t)row0 * NHD + col) =
                __floats2half2_rn(acc[mt][nt][0], acc[mt][nt][1]);
            *(__half2*)(g_h + (size_t)(row0 + 8) * NHD + col) =
                __floats2half2_rn(acc[mt][nt][2], acc[mt][nt][3]);
        }
    }

    // ---- epilogue 2: fused scores for this tile (64 rows x 2 heads) ----
    __syncthreads();
    float* sbuf = (float*)smem;           // 256 floats
    if (tid < 256) sbuf[tid] = 0.f;
    __syncthreads();

    const int hl = warp_n >> 6;
    const int cb = (warp_n & 32);
    float a1v[4][2], a2v[4][2];
    #pragma unroll
    for (int nt = 0; nt < 4; nt++)
        #pragma unroll
        for (int u = 0; u < 2; u++) {
            int ch = cb + nt * 8 + (lid & 3) * 2 + u;
            a1v[nt][u] = ga[ch];
            a2v[nt][u] = ga[64 + ch];
        }
    #pragma unroll
    for (int mt = 0; mt < 2; mt++) {
        float p1a = 0.f, p1b = 0.f, p2a = 0.f, p2b = 0.f;
        #pragma unroll
        for (int nt = 0; nt < 4; nt++) {
            p1a += acc[mt][nt][0] * a1v[nt][0] + acc[mt][nt][1] * a1v[nt][1];
            p1b += acc[mt][nt][2] * a1v[nt][0] + acc[mt][nt][3] * a1v[nt][1];
            p2a += acc[mt][nt][0] * a2v[nt][0] + acc[mt][nt][1] * a2v[nt][1];
            p2b += acc[mt][nt][2] * a2v[nt][0] + acc[mt][nt][3] * a2v[nt][1];
        }
        #pragma unroll
        for (int sh = 1; sh <= 2; sh <<= 1) {
            p1a += __shfl_xor_sync(0xffffffffu, p1a, sh);
            p1b += __shfl_xor_sync(0xffffffffu, p1b, sh);
            p2a += __shfl_xor_sync(0xffffffffu, p2a, sh);
            p2b += __shfl_xor_sync(0xffffffffu, p2b, sh);
        }
        if ((lid & 3) == 0) {
            int r0 = warp_m + mt * 16 + (lid >> 2);
            atomicAdd(&sbuf[(r0 * 2 + hl) * 2 + 0], p1a);
            atomicAdd(&sbuf[(r0 * 2 + hl) * 2 + 1], p2a);
            atomicAdd(&sbuf[((r0 + 8) * 2 + hl) * 2 + 0], p1b);
            atomicAdd(&sbuf[((r0 + 8) * 2 + hl) * 2 + 1], p2b);
        }
    }
    __syncthreads();
    if (tid < 128) {
        int row = tid >> 1, hd = tid & 1;
        int hg = (n0 >> 6) + hd;
        size_t mr = (size_t)(m0 + row);
        g_s1[mr * NH + hg] = sbuf[(row * 2 + hd) * 2 + 0];
        g_s2[mr * NH + hg] = sbuf[(row * 2 + hd) * 2 + 1];
    }
}

// ======================= aggregation: one block per node, both batches =======================
__global__ __launch_bounds__(256) void agg_kernel(
    float* __restrict__ out, const int* __restrict__ ei, int N, int E)
{
    const int n = blockIdx.x;
    const int tid = threadIdx.x;
    const int b = tid >> 7;            // warps 0-3: b=0, warps 4-7: b=1
    const int wtid = tid & 127;
    __shared__ float s[2][NHD];
    __shared__ float wv[2][NH];

    const int cnt = g_cnt[n];
    if (tid < 16) {
        int bb = tid >> 3, h = tid & 7;
        int le = g_last[n];            // e+1 encoding
        float w = 0.f;
        if (le > 0) {
            int dle = ei[E + (le - 1)];
            float sc0 = g_s1[((size_t)0 * N + n) * NH + h] + g_s2[((size_t)0 * N + dle) * NH + h];
            float sc1 = g_s1[((size_t)1 * N + n) * NH + h] + g_s2[((size_t)1 * N + dle) * NH + h];
            sc0 = sc0 > 0.f ? sc0 : 0.2f * sc0;
            sc1 = sc1 > 0.f ? sc1 : 0.2f * sc1;
            float m  = fmaxf(sc0, sc1);
            float e0 = expf(sc0 - m), e1 = expf(sc1 - m);
            float inv = 1.f / (e0 + e1);
            w = (bb == 0) ? e0 * inv : e1 * inv;
        }
        wv[bb][h] = w;
    }

    const int* bucket = g_csr + n * BUCKET;
    const __half* hbase = g_h + (size_t)b * N * NHD;
    float4 acc = make_float4(0.f, 0.f, 0.f, 0.f);
    int j = 0;
    for (; j + 3 < cnt; j += 4) {
        int d0 = bucket[j], d1 = bucket[j + 1], d2 = bucket[j + 2], d3 = bucket[j + 3];
        uint2 u0 = ((const uint2*)(hbase + (size_t)d0 * NHD))[wtid];
        uint2 u1 = ((const uint2*)(hbase + (size_t)d1 * NHD))[wtid];
        uint2 u2 = ((const uint2*)(hbase + (size_t)d2 * NHD))[wtid];
        uint2 u3 = ((const uint2*)(hbase + (size_t)d3 * NHD))[wtid];
        float2 f;
        f = __half22float2(*(__half2*)&u0.x); acc.x += f.x; acc.y += f.y;
        f = __half22float2(*(__half2*)&u0.y); acc.z += f.x; acc.w += f.y;
        f = __half22float2(*(__half2*)&u1.x); acc.x += f.x; acc.y += f.y;
        f = __half22float2(*(__half2*)&u1.y); acc.z += f.x; acc.w += f.y;
        f = __half22float2(*(__half2*)&u2.x); acc.x += f.x; acc.y += f.y;
        f = __half22float2(*(__half2*)&u2.y); acc.z += f.x; acc.w += f.y;
        f = __half22float2(*(__half2*)&u3.x); acc.x += f.x; acc.y += f.y;
        f = __half22float2(*(__half2*)&u3.y); acc.z += f.x; acc.w += f.y;
    }
    for (; j < cnt; j++) {
        int d = bucket[j];
        uint2 u0 = ((const uint2*)(hbase + (size_t)d * NHD))[wtid];
        float2 f;
        f = __half22float2(*(__half2*)&u0.x); acc.x += f.x; acc.y += f.y;
        f = __half22float2(*(__half2*)&u0.y); acc.z += f.x; acc.w += f.y;
    }
    ((float4*)s[b])[wtid] = acc;
    __syncthreads();
    if (wtid < ND) {
        float o = 0.f;
        #pragma unroll
        for (int h = 0; h < NH; h++) o += wv[b][h] * s[b][h * ND + wtid];
        out[((size_t)b * N + n) * ND + wtid] = o * 0.125f;
    }
    // restore zero state for the next graph replay (this block owns node n)
    if (tid == 0) { g_last[n] = 0; g_cnt[n] = 0; }
}

extern "C" void kernel_launch(void* const* d_in, const int* in_sizes, int n_in,
                              void* d_out, int out_size)
{
    const float* x  = (const float*)d_in[0];
    const int*   ei = (const int*)d_in[1];
    const float* W  = (const float*)d_in[2];
    const float* a  = (const float*)d_in[3];
    float* out = (float*)d_out;

    const int N = NN;
    const int E = in_sizes[1] / 2;

    cudaFuncSetAttribute(gemm_split, cudaFuncAttributeMaxDynamicSharedMemorySize, GEMM_SMEM);

    prep_kernel<<<(WQ + 65536 + 255) / 256, 256>>>(W, ei, E);
    gemm_split<<<dim3(NHD / 128, NM / 64), 256, GEMM_SMEM>>>(x, a);
    agg_kernel<<<NN, 256>>>(out, ei, N, E);
}

// round 15
// speedup vs baseline: 1.3923x; 1.3923x over previous
#include <cuda_runtime.h>
#include <cuda_fp16.h>
#include <math.h>
#include <stdint.h>

// Problem constants (fixed by the dataset)
#define NB 2
#define NN 8192
#define NF 512
#define NHD 512   // H*D
#define NH 8
#define ND 64
#define NM (NB * NN)   // 16384
#define BUCKET 64

// -------- scratch (device globals; zero-initialized at load; agg restores zeros) --------
__device__ __half g_h[NB * NN * NHD];                // 16 MB (fp16 h)
__device__ __half g_xh[NM * NF];                     // 16 MB (fp16 x)
__device__ __half g_wh[NHD * NF];                    // 0.5 MB (fp16 W)
__device__ float g_s1[NB * NN * NH];
__device__ float g_s2[NB * NN * NH];
__device__ int   g_last[NN];                         // e+1 encoding; 0 = no edge
__device__ int   g_cnt[NN];
__device__ int   g_csr[NN * BUCKET];                 // 2 MB

// ======================= helpers =======================
__device__ __forceinline__ uint32_t smem_u32(const void* p) {
    uint32_t a;
    asm("{ .reg .u64 t; cvta.to.shared.u64 t, %1; cvt.u32.u64 %0, t; }" : "=r"(a) : "l"(p));
    return a;
}
__device__ __forceinline__ void ldsm_x4(uint32_t* r, uint32_t addr) {
    asm volatile("ldmatrix.sync.aligned.m8n8.x4.shared.b16 {%0,%1,%2,%3}, [%4];"
        : "=r"(r[0]), "=r"(r[1]), "=r"(r[2]), "=r"(r[3]) : "r"(addr));
}
__device__ __forceinline__ void mma_fp16(float* d, const uint32_t* a, const uint32_t* b) {
    asm volatile("mma.sync.aligned.m16n8k16.row.col.f32.f16.f16.f32 "
        "{%0,%1,%2,%3}, {%4,%5,%6,%7}, {%8,%9}, {%0,%1,%2,%3};"
        : "+f"(d[0]), "+f"(d[1]), "+f"(d[2]), "+f"(d[3])
        : "r"(a[0]), "r"(a[1]), "r"(a[2]), "r"(a[3]), "r"(b[0]), "r"(b[1]));
}
__device__ __forceinline__ uint32_t hpack2(__half x, __half y) {
    uint32_t lo = __half_as_ushort(x), hi = __half_as_ushort(y);
    return (hi << 16) | lo;
}
__device__ __forceinline__ void cp16(uint32_t dst, const void* src) {
    asm volatile("cp.async.cg.shared.global [%0], [%1], 16;" :: "r"(dst), "l"(src));
}
#define CP_COMMIT() asm volatile("cp.async.commit_group;" ::: "memory")
#define CP_WAIT(n)  asm volatile("cp.async.wait_group %0;" :: "n"(n) : "memory")

// ======================= fused prep: conv(x), conv(W), edge build =======================
#define XQ (NM * NF / 4)
#define WQ (NHD * NF / 4)
__global__ __launch_bounds__(256) void prep_kernel(
    const float* __restrict__ x, const float* __restrict__ w,
    const int* __restrict__ ei, int E)
{
    size_t q = (size_t)blockIdx.x * blockDim.x + threadIdx.x;
    if (q < XQ) {
        size_t i = q * 4;
        float4 v = *(const float4*)(x + i);
        uint2 hi = make_uint2(hpack2(__float2half_rn(v.x), __float2half_rn(v.y)),
                              hpack2(__float2half_rn(v.z), __float2half_rn(v.w)));
        *(uint2*)(g_xh + i) = hi;
    } else if (q < XQ + WQ) {
        size_t i = (q - XQ) * 4;
        float4 v = *(const float4*)(w + i);
        uint2 hi = make_uint2(hpack2(__float2half_rn(v.x), __float2half_rn(v.y)),
                              hpack2(__float2half_rn(v.z), __float2half_rn(v.w)));
        *(uint2*)(g_wh + i) = hi;
    } else {
        int e = (int)(q - XQ - WQ);
        if (e < E) {
            int s = ei[e];
            atomicMax(&g_last[s], e + 1);          // +1: zero means "no edge"
            int p = atomicAdd(&g_cnt[s], 1);
            g_csr[s * BUCKET + p] = ei[E + e];
        }
    }
}

// ======================= fp16 single-term GEMM, 64x128 tile, 3 CTAs/SM =======================
#define TILE_A 4096
#define TILE_BB 8192
#define STAGE_B (TILE_A + TILE_BB)           // 12288: A, B
#define NSTAGE 3
#define GEMM_SMEM (NSTAGE * STAGE_B)         // 36864
#define NKC (NF / 32)                        // 16 chunks
#define OFF_A 0
#define OFF_BH TILE_A

__global__ __launch_bounds__(256, 3) void gemm_split(const float* __restrict__ ga)
{
    extern __shared__ char smem[];
    const uint32_t sb = smem_u32(smem);
    const int tid = threadIdx.x, wid = tid >> 5, lid = tid & 31;
    const int m0 = blockIdx.y * 64, n0 = blockIdx.x * 128;
    const int warp_m = (wid >> 2) * 32, warp_n = (wid & 3) * 32;

    const int aflr = tid >> 2;
    const uint32_t afu = (uint32_t)(aflr & 1) * 4 + (tid & 3);
    const uint32_t afm = ((uint32_t)aflr >> 1) & 7;
    const uint32_t adst = ((uint32_t)(aflr >> 1)) * 128 + ((afu ^ afm) << 4);
    const size_t  asrc = (size_t)(m0 + aflr) * NF + (tid & 3) * 8;

    const int bflr = tid >> 1, bfh = tid & 1;
    const uint32_t bfu = (uint32_t)(bflr & 1) * 4 + bfh * 2;
    const uint32_t bfm = ((uint32_t)bflr >> 1) & 7;
    const uint32_t bd0 = ((uint32_t)(bflr >> 1)) * 128 + ((bfu ^ bfm) << 4);
    const uint32_t bd1 = ((uint32_t)(bflr >> 1)) * 128 + (((bfu + 1) ^ bfm) << 4);
    const size_t  bsrc = (size_t)(n0 + bflr) * NF + bfh * 16;

    const int alr = warp_m + (lid & 15);
    const uint32_t a_row = ((uint32_t)(alr >> 1)) * 128;
    const uint32_t a4 = (uint32_t)(alr & 1) * 4 + (lid >> 4);
    const uint32_t amask = ((uint32_t)(alr >> 1)) & 7;
    const int blr = warp_n + (lid & 7) + (lid >> 4) * 8;
    const uint32_t b_row = ((uint32_t)(blr >> 1)) * 128;
    const uint32_t b4 = (uint32_t)(blr & 1) * 4 + ((lid >> 3) & 1);
    const uint32_t bmask = ((uint32_t)(blr >> 1)) & 7;

    float acc[2][4][4];
    #pragma unroll
    for (int i = 0; i < 2; i++)
        #pragma unroll
        for (int j = 0; j < 4; j++)
            #pragma unroll
            for (int v = 0; v < 4; v++) acc[i][j][v] = 0.f;

    auto issue = [&](int kc, int s) {
        const uint32_t base = sb + (uint32_t)s * STAGE_B;
        const int kcol = kc * 32;
        cp16(base + OFF_A + adst, g_xh + asrc + kcol);
        const __half* s2 = g_wh + bsrc + kcol;
        cp16(base + OFF_BH + bd0, s2);   cp16(base + OFF_BH + bd1, s2 + 8);
        CP_COMMIT();
    };

    issue(0, 0);
    issue(1, 1);

    int stg = 0;
    #pragma unroll 1
    for (int kc = 0; kc < NKC; kc++) {
        if (kc + 2 < NKC) { CP_WAIT(1); } else { CP_WAIT(0); }
        __syncthreads();
        if (kc + 2 < NKC) {
            int s2 = stg + 2; if (s2 >= NSTAGE) s2 -= NSTAGE;
            issue(kc + 2, s2);
        }
        {
            const uint32_t base = sb + (uint32_t)stg * STAGE_B;
            const uint32_t aH = base + OFF_A + a_row;
            const uint32_t bH = base + OFF_BH + b_row;
            #pragma unroll
            for (int ks = 0; ks < 2; ks++) {
                const uint32_t axo = ((a4 + 2 * ks) ^ amask) << 4;
                const uint32_t bxo = ((b4 + 2 * ks) ^ bmask) << 4;
                uint32_t bh[2][4];
                #pragma unroll
                for (int np = 0; np < 2; np++)
                    ldsm_x4(bh[np], bH + np * 1024 + bxo);
                #pragma unroll
                for (int mt = 0; mt < 2; mt++) {
                    uint32_t ah[4];
                    ldsm_x4(ah, aH + mt * 1024 + axo);
                    #pragma unroll
                    for (int nt = 0; nt < 4; nt++)
                        mma_fp16(acc[mt][nt], ah, &bh[nt >> 1][(nt & 1) * 2]);
                }
            }
        }
        stg++; if (stg >= NSTAGE) stg -= NSTAGE;
    }

    // ---- epilogue 1: write C as fp16 ----
    #pragma unroll
    for (int mt = 0; mt < 2; mt++) {
        const int row0 = m0 + warp_m + mt * 16 + (lid >> 2);
        #pragma unroll
        for (int nt = 0; nt < 4; nt++) {
            const int col = n0 + warp_n + nt * 8 + (lid & 3) * 2;
            *(__half2*)(g_h + (size_t)row0 * NHD + col) =
                __floats2half2_rn(acc[mt][nt][0], acc[mt][nt][1]);
            *(__half2*)(g_h + (size_t)(row0 + 8) * NHD + col) =
                __floats2half2_rn(acc[mt][nt][2], acc[mt][nt][3]);
        }
    }

    // ---- epilogue 2: fused scores for this tile (64 rows x 2 heads) ----
    __syncthreads();
    float* sbuf = (float*)smem;           // 256 floats
    if (tid < 256) sbuf[tid] = 0.f;
    __syncthreads();

    const int hl = warp_n >> 6;
    const int cb = (warp_n & 32);
    float a1v[4][2], a2v[4][2];
    #pragma unroll
    for (int nt = 0; nt < 4; nt++)
        #pragma unroll
        for (int u = 0; u < 2; u++) {
            int ch = cb + nt * 8 + (lid & 3) * 2 + u;
            a1v[nt][u] = ga[ch];
            a2v[nt][u] = ga[64 + ch];
        }
    #pragma unroll
    for (int mt = 0; mt < 2; mt++) {
        float p1a = 0.f, p1b = 0.f, p2a = 0.f, p2b = 0.f;
        #pragma unroll
        for (int nt = 0; nt < 4; nt++) {
            p1a += acc[mt][nt][0] * a1v[nt][0] + acc[mt][nt][1] * a1v[nt][1];
            p1b += acc[mt][nt][2] * a1v[nt][0] + acc[mt][nt][3] * a1v[nt][1];
            p2a += acc[mt][nt][0] * a2v[nt][0] + acc[mt][nt][1] * a2v[nt][1];
            p2b += acc[mt][nt][2] * a2v[nt][0] + acc[mt][nt][3] * a2v[nt][1];
        }
        #pragma unroll
        for (int sh = 1; sh <= 2; sh <<= 1) {
            p1a += __shfl_xor_sync(0xffffffffu, p1a, sh);
            p1b += __shfl_xor_sync(0xffffffffu, p1b, sh);
            p2a += __shfl_xor_sync(0xffffffffu, p2a, sh);
            p2b += __shfl_xor_sync(0xffffffffu, p2b, sh);
        }
        if ((lid & 3) == 0) {
            int r0 = warp_m + mt * 16 + (lid >> 2);
            atomicAdd(&sbuf[(r0 * 2 + hl) * 2 + 0], p1a);
            atomicAdd(&sbuf[(r0 * 2 + hl) * 2 + 1], p2a);
            atomicAdd(&sbuf[((r0 + 8) * 2 + hl) * 2 + 0], p1b);
            atomicAdd(&sbuf[((r0 + 8) * 2 + hl) * 2 + 1], p2b);
        }
    }
    __syncthreads();
    if (tid < 128) {
        int row = tid >> 1, hd = tid & 1;
        int hg = (n0 >> 6) + hd;
        size_t mr = (size_t)(m0 + row);
        g_s1[mr * NH + hg] = sbuf[(row * 2 + hd) * 2 + 0];
        g_s2[mr * NH + hg] = sbuf[(row * 2 + hd) * 2 + 1];
    }
}

// ======================= aggregation: one block per node, both batches =======================
__global__ __launch_bounds__(256) void agg_kernel(
    float* __restrict__ out, const int* __restrict__ ei, int N, int E)
{
    const int n = blockIdx.x;
    const int tid = threadIdx.x;
    const int b = tid >> 7;            // warps 0-3: b=0, warps 4-7: b=1
    const int wtid = tid & 127;
    __shared__ float s[2][NHD];
    __shared__ float wv[2][NH];

    const int cnt = g_cnt[n];
    if (tid < 16) {
        int bb = tid >> 3, h = tid & 7;
        int le = g_last[n];            // e+1 encoding
        float w = 0.f;
        if (le > 0) {
            int dle = ei[E + (le - 1)];
            float sc0 = g_s1[((size_t)0 * N + n) * NH + h] + g_s2[((size_t)0 * N + dle) * NH + h];
            float sc1 = g_s1[((size_t)1 * N + n) * NH + h] + g_s2[((size_t)1 * N + dle) * NH + h];
            sc0 = sc0 > 0.f ? sc0 : 0.2f * sc0;
            sc1 = sc1 > 0.f ? sc1 : 0.2f * sc1;
            float m  = fmaxf(sc0, sc1);
            float e0 = expf(sc0 - m), e1 = expf(sc1 - m);
            float inv = 1.f / (e0 + e1);
            w = (bb == 0) ? e0 * inv : e1 * inv;
        }
        wv[bb][h] = w;
    }

    const int* bucket = g_csr + n * BUCKET;
    const __half* hbase = g_h + (size_t)b * N * NHD;
    float4 acc = make_float4(0.f, 0.f, 0.f, 0.f);
    int j = 0;
    for (; j + 3 < cnt; j += 4) {
        int d0 = bucket[j], d1 = bucket[j + 1], d2 = bucket[j + 2], d3 = bucket[j + 3];
        uint2 u0 = ((const uint2*)(hbase + (size_t)d0 * NHD))[wtid];
        uint2 u1 = ((const uint2*)(hbase + (size_t)d1 * NHD))[wtid];
        uint2 u2 = ((const uint2*)(hbase + (size_t)d2 * NHD))[wtid];
        uint2 u3 = ((const uint2*)(hbase + (size_t)d3 * NHD))[wtid];
        float2 f;
        f = __half22float2(*(__half2*)&u0.x); acc.x += f.x; acc.y += f.y;
        f = __half22float2(*(__half2*)&u0.y); acc.z += f.x; acc.w += f.y;
        f = __half22float2(*(__half2*)&u1.x); acc.x += f.x; acc.y += f.y;
        f = __half22float2(*(__half2*)&u1.y); acc.z += f.x; acc.w += f.y;
        f = __half22float2(*(__half2*)&u2.x); acc.x += f.x; acc.y += f.y;
        f = __half22float2(*(__half2*)&u2.y); acc.z += f.x; acc.w += f.y;
        f = __half22float2(*(__half2*)&u3.x); acc.x += f.x; acc.y += f.y;
        f = __half22float2(*(__half2*)&u3.y); acc.z += f.x; acc.w += f.y;
    }
    for (; j < cnt; j++) {
        int d = bucket[j];
        uint2 u0 = ((const uint2*)(hbase + (size_t)d * NHD))[wtid];
        float2 f;
        f = __half22float2(*(__half2*)&u0.x); acc.x += f.x; acc.y += f.y;
        f = __half22float2(*(__half2*)&u0.y); acc.z += f.x; acc.w += f.y;
    }
    ((float4*)s[b])[wtid] = acc;
    __syncthreads();
    if (wtid < ND) {
        float o = 0.f;
        #pragma unroll
        for (int h = 0; h < NH; h++) o += wv[b][h] * s[b][h * ND + wtid];
        out[((size_t)b * N + n) * ND + wtid] = o * 0.125f;
    }
    // restore zero state for the next graph replay (this block owns node n)
    if (tid == 0) { g_last[n] = 0; g_cnt[n] = 0; }
}

extern "C" void kernel_launch(void* const* d_in, const int* in_sizes, int n_in,
                              void* d_out, int out_size)
{
    const float* x  = (const float*)d_in[0];
    const int*   ei = (const int*)d_in[1];
    const float* W  = (const float*)d_in[2];
    const float* a  = (const float*)d_in[3];
    float* out = (float*)d_out;

    const int N = NN;
    const int E = in_sizes[1] / 2;

    cudaFuncSetAttribute(gemm_split, cudaFuncAttributeMaxDynamicSharedMemorySize, GEMM_SMEM);

    const long total = (long)XQ + WQ + E;
    prep_kernel<<<(unsigned)((total + 255) / 256), 256>>>(x, W, ei, E);
    gemm_split<<<dim3(NHD / 128, NM / 64), 256, GEMM_SMEM>>>(a);
    agg_kernel<<<NN, 256>>>(out, ei, N, E);
}